// round 1
// baseline (speedup 1.0000x reference)
#include <cuda_runtime.h>
#include <math_constants.h>

static constexpr int K  = 1024;
static constexpr int D  = 64;
static constexpr int C  = 32;
static constexpr int NT = 256;       // threads per CTA
static constexpr int NW = NT / 32;   // warps per CTA

__global__ __launch_bounds__(NT) void nw_attn_kernel(
    const float* __restrict__ x,
    const float* __restrict__ keys,
    const float* __restrict__ values,
    const float* __restrict__ gamma,
    float* __restrict__ out)
{
    __shared__ float s_scores[K];      // 4 KB: scores then exp-weights
    __shared__ float s_red[NW];        // cross-warp reductions
    __shared__ float s_acc[C][C];      // [key-group][channel] partials

    const int b    = blockIdx.x;
    const int tid  = threadIdx.x;
    const int lane = tid & 31;
    const int warp = tid >> 5;
    const int half = lane >> 4;        // which of the 2 keys this lane serves
    const int l16  = lane & 15;        // dim-quad index within the key

    const float g = gamma[0];

    // x[b] slice for this lane's 4 dims (stays in registers for whole pass 1)
    const float4 xq = *reinterpret_cast<const float4*>(x + (size_t)b * D + 4 * l16);
    const float* kb = keys + (size_t)b * K * D;

    // ---------------- Pass 1: squared distances -> scores in smem ----------
    float lmax = -CUDART_INF_F;
    #pragma unroll 4
    for (int it = warp; it < K / 2; it += NW) {
        const int k = 2 * it + half;
        const float4 kq = __ldcs(reinterpret_cast<const float4*>(
                                     kb + (size_t)k * D + 4 * l16));
        const float d0 = xq.x - kq.x;
        const float d1 = xq.y - kq.y;
        const float d2 = xq.z - kq.z;
        const float d3 = xq.w - kq.w;
        float ss = d0 * d0 + d1 * d1 + d2 * d2 + d3 * d3;
        // reduce across the 16 lanes owning this key
        ss += __shfl_xor_sync(0xffffffffu, ss, 1);
        ss += __shfl_xor_sync(0xffffffffu, ss, 2);
        ss += __shfl_xor_sync(0xffffffffu, ss, 4);
        ss += __shfl_xor_sync(0xffffffffu, ss, 8);
        const float s = -g * ss;
        if (l16 == 0) s_scores[k] = s;
        lmax = fmaxf(lmax, s);
    }

    // ---------------- block max ----------------
    #pragma unroll
    for (int o = 16; o; o >>= 1)
        lmax = fmaxf(lmax, __shfl_xor_sync(0xffffffffu, lmax, o));
    if (lane == 0) s_red[warp] = lmax;
    __syncthreads();                   // scores + per-warp maxes visible
    float M = s_red[0];
    #pragma unroll
    for (int w = 1; w < NW; w++) M = fmaxf(M, s_red[w]);
    __syncthreads();                   // everyone has M before s_red reuse

    // ---------------- exp + block sum (smem only) ----------------
    float lsum = 0.f;
    #pragma unroll
    for (int k = tid; k < K; k += NT) {
        const float e = __expf(s_scores[k] - M);
        s_scores[k] = e;               // overwrite score with weight
        lsum += e;
    }
    #pragma unroll
    for (int o = 16; o; o >>= 1)
        lsum += __shfl_xor_sync(0xffffffffu, lsum, o);
    if (lane == 0) s_red[warp] = lsum;
    __syncthreads();                   // weights + partial sums visible
    float Z = 0.f;
    #pragma unroll
    for (int w = 0; w < NW; w++) Z += s_red[w];

    // ---------------- Pass 2: weighted sum over values ----------------
    // thread -> (key-group, channel-quad); warp loads 4 consecutive keys'
    // full 128B value rows = 512B contiguous per LDG.128 wave.
    const float* vb  = values + (size_t)b * K * C;
    const int kgrp = tid >> 3;         // 0..31
    const int cq   = (tid & 7) * 4;    // channel offset 0,4,...,28

    float4 acc = make_float4(0.f, 0.f, 0.f, 0.f);
    #pragma unroll 8
    for (int i = 0; i < K / 32; i++) {
        const int k = kgrp + 32 * i;
        const float w = s_scores[k];   // broadcast within 8-thread group
        const float4 v = __ldcs(reinterpret_cast<const float4*>(
                                    vb + (size_t)k * C + cq));
        acc.x += w * v.x;
        acc.y += w * v.y;
        acc.z += w * v.z;
        acc.w += w * v.w;
    }
    *reinterpret_cast<float4*>(&s_acc[kgrp][cq]) = acc;
    __syncthreads();

    if (tid < C) {
        float r = 0.f;
        #pragma unroll
        for (int gk = 0; gk < C; gk++) r += s_acc[gk][tid];
        out[(size_t)b * C + tid] = r * (1.0f / Z);
    }
}

extern "C" void kernel_launch(void* const* d_in, const int* in_sizes, int n_in,
                              void* d_out, int out_size)
{
    const float* x      = (const float*)d_in[0];
    const float* keys   = (const float*)d_in[1];
    const float* values = (const float*)d_in[2];
    const float* gamma  = (const float*)d_in[3];
    float* out = (float*)d_out;

    const int B = in_sizes[0] / D;     // 2048
    nw_attn_kernel<<<B, NT>>>(x, keys, values, gamma, out);
}

// round 3
// speedup vs baseline: 1.0891x; 1.0891x over previous
#include <cuda_runtime.h>
#include <math_constants.h>

static constexpr int K  = 1024;
static constexpr int D  = 64;
static constexpr int C  = 32;
static constexpr int NT = 256;       // threads per CTA
static constexpr int NW = NT / 32;   // warps per CTA

__global__ __launch_bounds__(NT) void nw_attn_kernel(
    const float* __restrict__ x,
    const float* __restrict__ keys,
    const float* __restrict__ values,
    const float* __restrict__ gamma,
    float* __restrict__ out)
{
    __shared__ float s_scores[K];          // 4 KB scores
    __shared__ float s_red[NW];            // per-warp max
    __shared__ float s_z[NW];              // per-warp Z partials
    __shared__ float s_acc[C][C + 1];      // padded rows: conflict-free column reads

    const int b    = blockIdx.x;
    const int tid  = threadIdx.x;
    const int lane = tid & 31;
    const int warp = tid >> 5;

    const float g = gamma[0];

    // ---- Pass 1: 4 lanes per key, 8 keys per warp-iter ----
    const int l4 = lane & 3;               // dim-group of 16 floats
    const int kw = lane >> 2;              // key within 8-key tile

    const float* xb = x + (size_t)b * D + l4 * 16;
    const float4 xq0 = *reinterpret_cast<const float4*>(xb + 0);
    const float4 xq1 = *reinterpret_cast<const float4*>(xb + 4);
    const float4 xq2 = *reinterpret_cast<const float4*>(xb + 8);
    const float4 xq3 = *reinterpret_cast<const float4*>(xb + 12);

    const float* kb = keys + (size_t)b * K * D;

    float lmax = -CUDART_INF_F;
    #pragma unroll 2
    for (int k0 = warp * 8; k0 < K; k0 += NW * 8) {   // 16 iters/warp
        const int key = k0 + kw;
        const float4* p = reinterpret_cast<const float4*>(
                              kb + (size_t)key * D + l4 * 16);
        // 4 independent 16B loads per lane (high MLP)
        const float4 a0 = __ldcs(p + 0);
        const float4 a1 = __ldcs(p + 1);
        const float4 a2 = __ldcs(p + 2);
        const float4 a3 = __ldcs(p + 3);

        float d, ss;
        d = xq0.x - a0.x; ss  = d * d;
        d = xq0.y - a0.y; ss = fmaf(d, d, ss);
        d = xq0.z - a0.z; ss = fmaf(d, d, ss);
        d = xq0.w - a0.w; ss = fmaf(d, d, ss);
        d = xq1.x - a1.x; ss = fmaf(d, d, ss);
        d = xq1.y - a1.y; ss = fmaf(d, d, ss);
        d = xq1.z - a1.z; ss = fmaf(d, d, ss);
        d = xq1.w - a1.w; ss = fmaf(d, d, ss);
        d = xq2.x - a2.x; ss = fmaf(d, d, ss);
        d = xq2.y - a2.y; ss = fmaf(d, d, ss);
        d = xq2.z - a2.z; ss = fmaf(d, d, ss);
        d = xq2.w - a2.w; ss = fmaf(d, d, ss);
        d = xq3.x - a3.x; ss = fmaf(d, d, ss);
        d = xq3.y - a3.y; ss = fmaf(d, d, ss);
        d = xq3.z - a3.z; ss = fmaf(d, d, ss);
        d = xq3.w - a3.w; ss = fmaf(d, d, ss);

        // reduce across the 4 lanes of this key
        ss += __shfl_xor_sync(0xffffffffu, ss, 1);
        ss += __shfl_xor_sync(0xffffffffu, ss, 2);

        const float s = -g * ss;
        if (l4 == 0) s_scores[key] = s;
        lmax = fmaxf(lmax, s);
    }

    // ---- block max ----
    #pragma unroll
    for (int o = 16; o; o >>= 1)
        lmax = fmaxf(lmax, __shfl_xor_sync(0xffffffffu, lmax, o));
    if (lane == 0) s_red[warp] = lmax;
    __syncthreads();                       // scores + maxes visible
    float M = s_red[0];
    #pragma unroll
    for (int w = 1; w < NW; w++) M = fmaxf(M, s_red[w]);

    // ---- Pass 2: exp on the fly + weighted sum over values ----
    const float* vb = values + (size_t)b * K * C;
    const int kgrp = tid >> 3;             // 0..31
    const int cq   = (tid & 7) * 4;        // channel offset
    const bool zlane = (tid & 7) == 0;

    float4 acc = make_float4(0.f, 0.f, 0.f, 0.f);
    float wsum = 0.f;
    #pragma unroll 8
    for (int i = 0; i < K / 32; i++) {
        const int k = kgrp + 32 * i;
        const float w = __expf(s_scores[k] - M);
        const float4 v = __ldcs(reinterpret_cast<const float4*>(
                                    vb + (size_t)k * C + cq));
        acc.x = fmaf(w, v.x, acc.x);
        acc.y = fmaf(w, v.y, acc.y);
        acc.z = fmaf(w, v.z, acc.z);
        acc.w = fmaf(w, v.w, acc.w);
        if (zlane) wsum += w;
    }

    // Z: warp reduce (only zlane contributed), then per-warp partials
    #pragma unroll
    for (int o = 16; o; o >>= 1)
        wsum += __shfl_xor_sync(0xffffffffu, wsum, o);
    if (lane == 0) s_z[warp] = wsum;

    // scalar stores: row stride 33 floats is not 16B-aligned, no STS.128
    s_acc[kgrp][cq + 0] = acc.x;
    s_acc[kgrp][cq + 1] = acc.y;
    s_acc[kgrp][cq + 2] = acc.z;
    s_acc[kgrp][cq + 3] = acc.w;
    __syncthreads();

    if (tid < C) {
        float Z = 0.f;
        #pragma unroll
        for (int w = 0; w < NW; w++) Z += s_z[w];
        float r = 0.f;
        #pragma unroll
        for (int gk = 0; gk < C; gk++) r += s_acc[gk][tid];
        out[(size_t)b * C + tid] = r * (1.0f / Z);
    }
}

extern "C" void kernel_launch(void* const* d_in, const int* in_sizes, int n_in,
                              void* d_out, int out_size)
{
    const float* x      = (const float*)d_in[0];
    const float* keys   = (const float*)d_in[1];
    const float* values = (const float*)d_in[2];
    const float* gamma  = (const float*)d_in[3];
    float* out = (float*)d_out;

    const int B = in_sizes[0] / D;     // 2048
    nw_attn_kernel<<<B, NT>>>(x, keys, values, gamma, out);
}